// round 3
// baseline (speedup 1.0000x reference)
#include <cuda_runtime.h>
#include <cuda_bf16.h>
#include <cstdint>

#define NB2 128   // persistent blocks in recurrent kernel (must be <= 148)

// ------------------------------------------------------------------
// Device-global scratch (allocation-free)
// ------------------------------------------------------------------
__device__ float d_Gx[(size_t)16384 * 4096];     // x@Wx + bias, row=b*512+t, col=gate*1024+j
__device__ float d_H2[(size_t)16384 * 1024];     // h in [b*512+t][j] layout (for final FC)
__device__ float d_Hts[(size_t)513 * 32 * 1024]; // h in [t][b][k_perm] layout (for recurrence)
__device__ float d_Wx[(size_t)512 * 4096];       // packed input-projection weights
__device__ float d_bx[4096];                     // packed gate biases
__device__ unsigned d_cnt[512];                  // per-step grid-barrier counters

// ------------------------------------------------------------------
// Helpers
// ------------------------------------------------------------------
__device__ __forceinline__ unsigned cvt_tf32(float x) {
    unsigned u;
    asm("cvt.rna.tf32.f32 %0, %1;" : "=r"(u) : "f"(x));
    return u;
}

__device__ __forceinline__ void mma_tf32(float c[4],
                                         unsigned a0, unsigned a1, unsigned a2, unsigned a3,
                                         unsigned b0, unsigned b1) {
    asm volatile(
        "mma.sync.aligned.m16n8k8.row.col.f32.tf32.tf32.f32 "
        "{%0,%1,%2,%3},{%4,%5,%6,%7},{%8,%9},{%0,%1,%2,%3};"
        : "+f"(c[0]), "+f"(c[1]), "+f"(c[2]), "+f"(c[3])
        : "r"(a0), "r"(a1), "r"(a2), "r"(a3), "r"(b0), "r"(b1));
}

__device__ __forceinline__ float sigm(float x) { return 1.f / (1.f + __expf(-x)); }

__device__ __forceinline__ void cpa16(float* s, const float* g) {
    unsigned sa = (unsigned)__cvta_generic_to_shared(s);
    asm volatile("cp.async.ca.shared.global [%0], [%1], 16;" :: "r"(sa), "l"(g));
}

__device__ __forceinline__ float4 ldcg4(const float* p) {
    return __ldcg((const float4*)p);
}

// ------------------------------------------------------------------
// Init: zero h_0 slab and barrier counters (runs every launch/replay)
// ------------------------------------------------------------------
__global__ void init_kernel() {
    int idx = blockIdx.x * blockDim.x + threadIdx.x;
    if (idx < 32768) d_Hts[idx] = 0.f;
    if (idx < 512) d_cnt[idx] = 0u;
}

// ------------------------------------------------------------------
// Pack Wx = [Wf|Wi|Wg|Wo] rows [0,512), and the gate biases
// ------------------------------------------------------------------
__global__ void pack_kernel(const float* __restrict__ Wf, const float* __restrict__ Wi,
                            const float* __restrict__ Wg, const float* __restrict__ Wo,
                            const float* __restrict__ bf, const float* __restrict__ bi,
                            const float* __restrict__ bg, const float* __restrict__ bo) {
    int idx = blockIdx.x * blockDim.x + threadIdx.x;
    if (idx < 512 * 1024) {
        int k = idx >> 10, j = idx & 1023;
        size_t o = (size_t)k * 4096 + j;
        d_Wx[o]        = Wf[idx];
        d_Wx[o + 1024] = Wi[idx];
        d_Wx[o + 2048] = Wg[idx];
        d_Wx[o + 3072] = Wo[idx];
    }
    if (idx < 1024) {
        d_bx[idx]        = bf[idx];
        d_bx[idx + 1024] = bi[idx];
        d_bx[idx + 2048] = bg[idx];
        d_bx[idx + 3072] = bo[idx];
    }
}

// ------------------------------------------------------------------
// tf32 GEMM: C[M,N] = A[M,K] @ B[K,N] + bias[N]
// 128x128x16 tiles, 8 warps (warp tile 64x32), cp.async double buffer.
// Requires M%128==0, N%128==0, K%16==0 (true for all our shapes).
// ------------------------------------------------------------------
__device__ __forceinline__ void g_issue(const float* A, const float* Bm,
                                        int N, int K, int m0, int n0, int k0,
                                        float* sA, float* sB, int tid) {
#pragma unroll
    for (int i = 0; i < 2; i++) {
        int lin = tid + i * 256;
        int r = lin >> 2, q = lin & 3;              // 128 rows x 4 quads
        cpa16(sA + r * 20 + q * 4, A + (size_t)(m0 + r) * K + k0 + q * 4);
    }
#pragma unroll
    for (int i = 0; i < 2; i++) {
        int lin = tid + i * 256;
        int r = lin >> 5, q = lin & 31;             // 16 rows x 32 quads
        cpa16(sB + r * 132 + q * 4, Bm + (size_t)(k0 + r) * N + n0 + q * 4);
    }
    asm volatile("cp.async.commit_group;" ::: "memory");
}

__global__ void __launch_bounds__(256) gemm_tf32_bias(
    const float* __restrict__ A, const float* __restrict__ Bm,
    const float* __restrict__ bias, float* __restrict__ C,
    int M, int N, int K) {
    __shared__ float sA[2][128 * 20];
    __shared__ float sB[2][16 * 132];

    const int tid = threadIdx.x;
    const int w = tid >> 5, lane = tid & 31;
    const int g = lane >> 2, tig = lane & 3;
    const int wm = (w >> 2) * 64, wn = (w & 3) * 32;
    const int m0 = blockIdx.y * 128, n0 = blockIdx.x * 128;

    float Cr[4][4][4];
#pragma unroll
    for (int a = 0; a < 4; a++)
#pragma unroll
        for (int b = 0; b < 4; b++)
#pragma unroll
            for (int c = 0; c < 4; c++) Cr[a][b][c] = 0.f;

    const int nk = K / 16;
    g_issue(A, Bm, N, K, m0, n0, 0, sA[0], sB[0], tid);

    for (int kc = 0; kc < nk; kc++) {
        if (kc + 1 < nk) {
            g_issue(A, Bm, N, K, m0, n0, (kc + 1) * 16, sA[(kc + 1) & 1], sB[(kc + 1) & 1], tid);
            asm volatile("cp.async.wait_group 1;" ::: "memory");
        } else {
            asm volatile("cp.async.wait_group 0;" ::: "memory");
        }
        __syncthreads();

        const float* bA = sA[kc & 1];
        const float* bB = sB[kc & 1];
#pragma unroll
        for (int k8 = 0; k8 < 2; k8++) {
            unsigned bf_[4][2];
#pragma unroll
            for (int nt = 0; nt < 4; nt++) {
                bf_[nt][0] = cvt_tf32(bB[(k8 * 8 + tig) * 132 + wn + nt * 8 + g]);
                bf_[nt][1] = cvt_tf32(bB[(k8 * 8 + tig + 4) * 132 + wn + nt * 8 + g]);
            }
#pragma unroll
            for (int mt = 0; mt < 4; mt++) {
                const float* ap = bA + (wm + mt * 16 + g) * 20 + k8 * 8 + tig;
                unsigned a0 = cvt_tf32(ap[0]);
                unsigned a1 = cvt_tf32(ap[8 * 20]);
                unsigned a2 = cvt_tf32(ap[4]);
                unsigned a3 = cvt_tf32(ap[8 * 20 + 4]);
#pragma unroll
                for (int nt = 0; nt < 4; nt++)
                    mma_tf32(Cr[mt][nt], a0, a1, a2, a3, bf_[nt][0], bf_[nt][1]);
            }
        }
        __syncthreads();   // compute done before this buffer is refilled
    }

    // Epilogue: add bias, store
#pragma unroll
    for (int mt = 0; mt < 4; mt++) {
#pragma unroll
        for (int nt = 0; nt < 4; nt++) {
            int row = m0 + wm + mt * 16 + g;
            int col = n0 + wn + nt * 8 + 2 * tig;
            float bx = bias[col], by = bias[col + 1];
            float2 v0 = make_float2(Cr[mt][nt][0] + bx, Cr[mt][nt][1] + by);
            float2 v1 = make_float2(Cr[mt][nt][2] + bx, Cr[mt][nt][3] + by);
            *(float2*)(C + (size_t)row * N + col) = v0;
            *(float2*)(C + (size_t)(row + 8) * N + col) = v1;
        }
    }
}

// ------------------------------------------------------------------
// Persistent recurrent kernel. 128 blocks x 256 threads (8 warps).
// Block bk owns hidden units [bk*8, bk*8+8) x 4 gates (32 gate cols).
// Wh slice lives in registers as tf32 B-fragments (loaded once).
// h is stored [t][b][k_perm]: within each 16-k group, position
// 16a + 4t + s holds k = 16a + t + 4s, so ONE float4 per lane yields
// the (a0,a2) elements of two adjacent k8 MMA tiles.
// ------------------------------------------------------------------
__global__ void __launch_bounds__(256) lstm_rec(
    const float* __restrict__ Wf, const float* __restrict__ Wi,
    const float* __restrict__ Wg, const float* __restrict__ Wo) {
    __shared__ float sPart[8 * 1056];  // 8 warps x 32x32 partials (row stride 33)

    const int tid = threadIdx.x;
    const int w = tid >> 5, lane = tid & 31;
    const int g = lane >> 2, tig = lane & 3;
    const int kw = w * 128;            // this warp's K-slice base
    const int bk = blockIdx.x;

    // ---- Preload weights into registers as tf32 B-fragments (true k order) ----
    const float* Wp[4] = {Wf, Wi, Wg, Wo};
    unsigned Wr[16][4][2];
#pragma unroll
    for (int kt = 0; kt < 16; kt++) {
#pragma unroll
        for (int nt = 0; nt < 4; nt++) {
            const float* ws = Wp[nt] + (size_t)(512 + kw + kt * 8 + tig) * 1024 + bk * 8 + g;
            Wr[kt][nt][0] = cvt_tf32(__ldg(ws));
            Wr[kt][nt][1] = cvt_tf32(__ldg(ws + 4 * 1024));
        }
    }

    // State-update thread mapping: b = tid/8, uu = tid%8
    const int b_ = tid >> 3, uu = tid & 7;
    float creg = 0.f;

    // permuted k position for this thread's hidden unit
    const int j = bk * 8 + uu;
    const int pp = (j & ~15) + 4 * (j & 3) + ((j & 15) >> 2);

    const float* gxbase = d_Gx + (size_t)(b_ * 512) * 4096 + bk * 8 + uu;

    for (int t = 0; t < 512; t++) {
        // Prefetch this step's input-projection gate values (independent of h)
        const float* gxp = gxbase + (size_t)t * 4096;
        float gx0 = __ldg(gxp);
        float gx1 = __ldg(gxp + 1024);
        float gx2 = __ldg(gxp + 2048);
        float gx3 = __ldg(gxp + 3072);

        // ---- h_t @ Wh_slice : each warp reduces its K=128 slice ----
        float Cr[2][4][4];
#pragma unroll
        for (int mt = 0; mt < 2; mt++)
#pragma unroll
            for (int nt = 0; nt < 4; nt++)
#pragma unroll
                for (int c = 0; c < 4; c++) Cr[mt][nt][c] = 0.f;

        const float* htp = d_Hts + (size_t)t * 32768 + kw + 4 * tig;
#pragma unroll
        for (int ks = 0; ks < 8; ks++) {           // 16-k groups
            const float* base = htp + ks * 16;
#pragma unroll
            for (int mt = 0; mt < 2; mt++) {
                float4 v0 = ldcg4(base + (mt * 16 + g) * 1024);
                float4 v1 = ldcg4(base + (mt * 16 + g + 8) * 1024);
                unsigned a0 = cvt_tf32(v0.x), a2 = cvt_tf32(v0.y);
                unsigned a1 = cvt_tf32(v1.x), a3 = cvt_tf32(v1.y);
                unsigned c0 = cvt_tf32(v0.z), c2 = cvt_tf32(v0.w);
                unsigned c1 = cvt_tf32(v1.z), c3 = cvt_tf32(v1.w);
#pragma unroll
                for (int nt = 0; nt < 4; nt++)
                    mma_tf32(Cr[mt][nt], a0, a1, a2, a3, Wr[2 * ks][nt][0], Wr[2 * ks][nt][1]);
#pragma unroll
                for (int nt = 0; nt < 4; nt++)
                    mma_tf32(Cr[mt][nt], c0, c1, c2, c3, Wr[2 * ks + 1][nt][0], Wr[2 * ks + 1][nt][1]);
            }
        }

        // ---- Store per-warp partials to smem ----
        {
            float* sp = sPart + w * 1056;
#pragma unroll
            for (int mt = 0; mt < 2; mt++) {
#pragma unroll
                for (int nt = 0; nt < 4; nt++) {
                    int row = mt * 16 + g, col = nt * 8 + 2 * tig;
                    sp[row * 33 + col]           = Cr[mt][nt][0];
                    sp[row * 33 + col + 1]       = Cr[mt][nt][1];
                    sp[(row + 8) * 33 + col]     = Cr[mt][nt][2];
                    sp[(row + 8) * 33 + col + 1] = Cr[mt][nt][3];
                }
            }
        }
        __syncthreads();

        // ---- Cross-warp reduce + gate nonlinearity + state update ----
        float red[4];
#pragma unroll
        for (int gate = 0; gate < 4; gate++) {
            float s = 0.f;
#pragma unroll
            for (int w2 = 0; w2 < 8; w2++)
                s += sPart[w2 * 1056 + b_ * 33 + gate * 8 + uu];
            red[gate] = s;
        }
        float F = red[0] + gx0;
        float I = red[1] + gx1;
        float G = red[2] + gx2;
        float O = red[3] + gx3;
        creg = sigm(F) * creg + sigm(I) * tanhf(G);
        float h = sigm(O) * tanhf(creg);

        // Write h in both layouts (recurrent: permuted position)
        d_Hts[(size_t)(t + 1) * 32768 + b_ * 1024 + pp] = h;
        d_H2[(size_t)(b_ * 512 + t) * 1024 + bk * 8 + uu] = h;

        // ---- Grid barrier ----
        __syncthreads();   // also protects sPart reuse next step
        __threadfence();
        if (tid == 0) {
            unsigned arrived = atomicAdd(&d_cnt[t], 1u) + 1u;
            if (arrived < NB2) {
                volatile unsigned* vc = d_cnt;
                while (vc[t] < NB2) {}
            }
        }
        __syncthreads();
    }
}

// ------------------------------------------------------------------
// Launch sequence (graph-capturable: kernel launches only)
// ------------------------------------------------------------------
extern "C" void kernel_launch(void* const* d_in, const int* in_sizes, int n_in,
                              void* d_out, int out_size) {
    const float* x    = (const float*)d_in[0];
    const float* W_f  = (const float*)d_in[1];
    const float* b_f  = (const float*)d_in[2];
    const float* W_i  = (const float*)d_in[3];
    const float* b_i  = (const float*)d_in[4];
    const float* W_g  = (const float*)d_in[5];
    const float* b_g  = (const float*)d_in[6];
    const float* W_o  = (const float*)d_in[7];
    const float* b_o  = (const float*)d_in[8];
    const float* W_fc = (const float*)d_in[9];
    const float* b_fc = (const float*)d_in[10];
    float* out = (float*)d_out;

    void *pGx, *pH2, *pWx, *pbx;
    cudaGetSymbolAddress(&pGx, d_Gx);
    cudaGetSymbolAddress(&pH2, d_H2);
    cudaGetSymbolAddress(&pWx, d_Wx);
    cudaGetSymbolAddress(&pbx, d_bx);

    init_kernel<<<128, 256>>>();
    pack_kernel<<<2048, 256>>>(W_f, W_i, W_g, W_o, b_f, b_i, b_g, b_o);

    // Phase 1: Gx = x @ Wx + bx   (M=16384, N=4096, K=512)
    gemm_tf32_bias<<<dim3(32, 128), 256>>>(
        x, (const float*)pWx, (const float*)pbx, (float*)pGx, 16384, 4096, 512);

    // Phase 2: recurrence (persistent)
    lstm_rec<<<NB2, 256>>>(W_f, W_i, W_g, W_o);

    // Phase 3: out = H2 @ W_fc + b_fc   (M=16384, N=512, K=1024)
    gemm_tf32_bias<<<dim3(4, 128), 256>>>(
        (const float*)pH2, W_fc, b_fc, out, 16384, 512, 1024);
}

// round 4
// speedup vs baseline: 1.2120x; 1.2120x over previous
#include <cuda_runtime.h>
#include <cuda_bf16.h>
#include <cstdint>

#define NB2 128   // persistent blocks in recurrent kernel (must be <= 148)

// ------------------------------------------------------------------
// Device-global scratch (allocation-free)
// ------------------------------------------------------------------
__device__ float d_Gx[(size_t)16384 * 4096];     // x@Wx + bias, row=b*512+t, col=gate*1024+j
__device__ float d_H2[(size_t)16384 * 1024];     // h in [b*512+t][j] layout (for final FC)
__device__ float d_Hts[(size_t)513 * 32 * 1024]; // h in [t][b][k_perm] layout (for recurrence)
__device__ float d_Wx[(size_t)512 * 4096];       // packed input-projection weights
__device__ float d_bx[4096];                     // packed gate biases
__device__ unsigned d_cnt[512];                  // per-step grid-barrier counters

// ------------------------------------------------------------------
// Helpers
// ------------------------------------------------------------------
__device__ __forceinline__ unsigned cvt_tf32(float x) {
    unsigned u;
    asm("cvt.rna.tf32.f32 %0, %1;" : "=r"(u) : "f"(x));
    return u;
}

__device__ __forceinline__ void mma_tf32(float c[4],
                                         unsigned a0, unsigned a1, unsigned a2, unsigned a3,
                                         unsigned b0, unsigned b1) {
    asm volatile(
        "mma.sync.aligned.m16n8k8.row.col.f32.tf32.tf32.f32 "
        "{%0,%1,%2,%3},{%4,%5,%6,%7},{%8,%9},{%0,%1,%2,%3};"
        : "+f"(c[0]), "+f"(c[1]), "+f"(c[2]), "+f"(c[3])
        : "r"(a0), "r"(a1), "r"(a2), "r"(a3), "r"(b0), "r"(b1));
}

__device__ __forceinline__ float sigm(float x) { return 1.f / (1.f + __expf(-x)); }

__device__ __forceinline__ float4 ldcg4(const float* p) {
    return __ldcg((const float4*)p);
}

// ------------------------------------------------------------------
// Init: zero h_0 slab and barrier counters (runs every launch/replay)
// ------------------------------------------------------------------
__global__ void init_kernel() {
    int idx = blockIdx.x * blockDim.x + threadIdx.x;
    if (idx < 32768) d_Hts[idx] = 0.f;
    if (idx < 512) d_cnt[idx] = 0u;
}

// ------------------------------------------------------------------
// Pack Wx = [Wf|Wi|Wg|Wo] rows [0,512), and the gate biases
// ------------------------------------------------------------------
__global__ void pack_kernel(const float* __restrict__ Wf, const float* __restrict__ Wi,
                            const float* __restrict__ Wg, const float* __restrict__ Wo,
                            const float* __restrict__ bf, const float* __restrict__ bi,
                            const float* __restrict__ bg, const float* __restrict__ bo) {
    int idx = blockIdx.x * blockDim.x + threadIdx.x;
    if (idx < 512 * 1024) {
        int k = idx >> 10, j = idx & 1023;
        size_t o = (size_t)k * 4096 + j;
        d_Wx[o]        = Wf[idx];
        d_Wx[o + 1024] = Wi[idx];
        d_Wx[o + 2048] = Wg[idx];
        d_Wx[o + 3072] = Wo[idx];
    }
    if (idx < 1024) {
        d_bx[idx]        = bf[idx];
        d_bx[idx + 1024] = bi[idx];
        d_bx[idx + 2048] = bg[idx];
        d_bx[idx + 3072] = bo[idx];
    }
}

// ------------------------------------------------------------------
// tf32 GEMM: C[M,N] = A[M,K] @ B[K,N] + bias[N]
// 128x128x16 tiles, 8 warps (warp tile 64x32), single-buffered smem.
// (The cp.async double-buffered variant measured SLOWER in R3; reverted.)
// Requires M%128==0, N%128==0, K%16==0 (true for all our shapes).
// ------------------------------------------------------------------
__global__ void __launch_bounds__(256) gemm_tf32_bias(
    const float* __restrict__ A, const float* __restrict__ Bm,
    const float* __restrict__ bias, float* __restrict__ C,
    int M, int N, int K) {
    __shared__ float sA[128 * 20];  // 128 rows x 16 (+4 pad)
    __shared__ float sB[16 * 132];  // 16 rows x 128 (+4 pad)

    const int tid = threadIdx.x;
    const int w = tid >> 5, lane = tid & 31;
    const int g = lane >> 2, tig = lane & 3;
    const int wm = (w >> 2) * 64, wn = (w & 3) * 32;
    const int m0 = blockIdx.y * 128, n0 = blockIdx.x * 128;

    float Cr[4][4][4];
#pragma unroll
    for (int a = 0; a < 4; a++)
#pragma unroll
        for (int b = 0; b < 4; b++)
#pragma unroll
            for (int c = 0; c < 4; c++) Cr[a][b][c] = 0.f;

    const int nk = K / 16;
    for (int kc = 0; kc < nk; kc++) {
        const int k0 = kc * 16;
        __syncthreads();
#pragma unroll
        for (int i = 0; i < 2; i++) {
            int lin = tid + i * 256;
            int r = lin >> 2, q = lin & 3;
            float4 v = *(const float4*)(A + (size_t)(m0 + r) * K + k0 + q * 4);
            *(float4*)(sA + r * 20 + q * 4) = v;
        }
#pragma unroll
        for (int i = 0; i < 2; i++) {
            int lin = tid + i * 256;
            int r = lin >> 5, q = lin & 31;
            float4 v = *(const float4*)(Bm + (size_t)(k0 + r) * N + n0 + q * 4);
            *(float4*)(sB + r * 132 + q * 4) = v;
        }
        __syncthreads();

#pragma unroll
        for (int k8 = 0; k8 < 2; k8++) {
            unsigned bf_[4][2];
#pragma unroll
            for (int nt = 0; nt < 4; nt++) {
                bf_[nt][0] = cvt_tf32(sB[(k8 * 8 + tig) * 132 + wn + nt * 8 + g]);
                bf_[nt][1] = cvt_tf32(sB[(k8 * 8 + tig + 4) * 132 + wn + nt * 8 + g]);
            }
#pragma unroll
            for (int mt = 0; mt < 4; mt++) {
                const float* ap = sA + (wm + mt * 16 + g) * 20 + k8 * 8 + tig;
                unsigned a0 = cvt_tf32(ap[0]);
                unsigned a1 = cvt_tf32(ap[8 * 20]);
                unsigned a2 = cvt_tf32(ap[4]);
                unsigned a3 = cvt_tf32(ap[8 * 20 + 4]);
#pragma unroll
                for (int nt = 0; nt < 4; nt++)
                    mma_tf32(Cr[mt][nt], a0, a1, a2, a3, bf_[nt][0], bf_[nt][1]);
            }
        }
    }

    // Epilogue: add bias, store
#pragma unroll
    for (int mt = 0; mt < 4; mt++) {
#pragma unroll
        for (int nt = 0; nt < 4; nt++) {
            int row = m0 + wm + mt * 16 + g;
            int col = n0 + wn + nt * 8 + 2 * tig;
            float bx = bias[col], by = bias[col + 1];
            float2 v0 = make_float2(Cr[mt][nt][0] + bx, Cr[mt][nt][1] + by);
            float2 v1 = make_float2(Cr[mt][nt][2] + bx, Cr[mt][nt][3] + by);
            *(float2*)(C + (size_t)row * N + col) = v0;
            *(float2*)(C + (size_t)(row + 8) * N + col) = v1;
        }
    }
}

// ------------------------------------------------------------------
// Persistent recurrent kernel. 128 blocks x 512 threads (16 warps).
// Block bk owns hidden units [bk*8, bk*8+8) x 4 gates (32 gate cols).
// Warp w owns K-slice [w*64, w*64+64). Wh fragments in registers
// (Wr[8][4][2] = 64 regs/thread, loaded once).
// h stored [t][b][k_perm]: within each 16-k group, position
// 16a + 4t + s holds k = 16a + t + 4s, so ONE float4 per lane yields
// the (a0,a2) elements of two adjacent k8 MMA tiles.
// Two-stage reduction: warps 8-15 write partials to 8 smem regions,
// warps 0-7 accumulate in place, state threads sum 8 regions.
// ------------------------------------------------------------------
__global__ void __launch_bounds__(512) lstm_rec(
    const float* __restrict__ Wf, const float* __restrict__ Wi,
    const float* __restrict__ Wg, const float* __restrict__ Wo) {
    __shared__ float sPart[8 * 1056];  // 8 regions x 32x32 partials (row stride 33)

    const int tid = threadIdx.x;
    const int w = tid >> 5, lane = tid & 31;
    const int g = lane >> 2, tig = lane & 3;
    const int kw = w * 64;             // this warp's K-slice base
    const int bk = blockIdx.x;

    // ---- Preload weights into registers as tf32 B-fragments (true k order) ----
    const float* Wp[4] = {Wf, Wi, Wg, Wo};
    unsigned Wr[8][4][2];
#pragma unroll
    for (int kt = 0; kt < 8; kt++) {
#pragma unroll
        for (int nt = 0; nt < 4; nt++) {
            const float* ws = Wp[nt] + (size_t)(512 + kw + kt * 8 + tig) * 1024 + bk * 8 + g;
            Wr[kt][nt][0] = cvt_tf32(__ldg(ws));
            Wr[kt][nt][1] = cvt_tf32(__ldg(ws + 4 * 1024));
        }
    }

    // State-update thread mapping (first 256 threads): b = tid/8, uu = tid%8
    const int b_ = (tid >> 3) & 31, uu = tid & 7;
    const bool is_state = tid < 256;
    float creg = 0.f;

    // permuted k position for this thread's hidden unit
    const int j = bk * 8 + uu;
    const int pp = (j & ~15) + 4 * (j & 3) + ((j & 15) >> 2);

    const float* gxbase = d_Gx + (size_t)(b_ * 512) * 4096 + bk * 8 + uu;

    for (int t = 0; t < 512; t++) {
        // Prefetch this step's input-projection gate values (independent of h)
        float gx0 = 0.f, gx1 = 0.f, gx2 = 0.f, gx3 = 0.f;
        if (is_state) {
            const float* gxp = gxbase + (size_t)t * 4096;
            gx0 = __ldcs(gxp);
            gx1 = __ldcs(gxp + 1024);
            gx2 = __ldcs(gxp + 2048);
            gx3 = __ldcs(gxp + 3072);
        }

        // ---- h_t @ Wh_slice : each warp reduces its K=64 slice ----
        float Cr[2][4][4];
#pragma unroll
        for (int mt = 0; mt < 2; mt++)
#pragma unroll
            for (int nt = 0; nt < 4; nt++)
#pragma unroll
                for (int c = 0; c < 4; c++) Cr[mt][nt][c] = 0.f;

        const float* htp = d_Hts + (size_t)t * 32768 + kw + 4 * tig;
#pragma unroll
        for (int ks = 0; ks < 4; ks++) {           // 16-k groups in this warp's slice
            const float* base = htp + ks * 16;
#pragma unroll
            for (int mt = 0; mt < 2; mt++) {
                float4 v0 = ldcg4(base + (mt * 16 + g) * 1024);
                float4 v1 = ldcg4(base + (mt * 16 + g + 8) * 1024);
                unsigned a0 = cvt_tf32(v0.x), a2 = cvt_tf32(v0.y);
                unsigned a1 = cvt_tf32(v1.x), a3 = cvt_tf32(v1.y);
                unsigned c0 = cvt_tf32(v0.z), c2 = cvt_tf32(v0.w);
                unsigned c1 = cvt_tf32(v1.z), c3 = cvt_tf32(v1.w);
#pragma unroll
                for (int nt = 0; nt < 4; nt++)
                    mma_tf32(Cr[mt][nt], a0, a1, a2, a3, Wr[2 * ks][nt][0], Wr[2 * ks][nt][1]);
#pragma unroll
                for (int nt = 0; nt < 4; nt++)
                    mma_tf32(Cr[mt][nt], c0, c1, c2, c3, Wr[2 * ks + 1][nt][0], Wr[2 * ks + 1][nt][1]);
            }
        }

        // ---- Stage 1: warps 8-15 write partials to region (w-8) ----
        if (w >= 8) {
            float* sp = sPart + (w - 8) * 1056;
#pragma unroll
            for (int mt = 0; mt < 2; mt++) {
#pragma unroll
                for (int nt = 0; nt < 4; nt++) {
                    int row = mt * 16 + g, col = nt * 8 + 2 * tig;
                    sp[row * 33 + col]           = Cr[mt][nt][0];
                    sp[row * 33 + col + 1]       = Cr[mt][nt][1];
                    sp[(row + 8) * 33 + col]     = Cr[mt][nt][2];
                    sp[(row + 8) * 33 + col + 1] = Cr[mt][nt][3];
                }
            }
        }
        __syncthreads();

        // ---- Stage 2: warps 0-7 accumulate in place into region w ----
        if (w < 8) {
            float* sp = sPart + w * 1056;
#pragma unroll
            for (int mt = 0; mt < 2; mt++) {
#pragma unroll
                for (int nt = 0; nt < 4; nt++) {
                    int row = mt * 16 + g, col = nt * 8 + 2 * tig;
                    sp[row * 33 + col]           += Cr[mt][nt][0];
                    sp[row * 33 + col + 1]       += Cr[mt][nt][1];
                    sp[(row + 8) * 33 + col]     += Cr[mt][nt][2];
                    sp[(row + 8) * 33 + col + 1] += Cr[mt][nt][3];
                }
            }
        }
        __syncthreads();

        // ---- Final reduce + gate nonlinearity + state update ----
        if (is_state) {
            float red[4];
#pragma unroll
            for (int gate = 0; gate < 4; gate++) {
                float s = 0.f;
#pragma unroll
                for (int w2 = 0; w2 < 8; w2++)
                    s += sPart[w2 * 1056 + b_ * 33 + gate * 8 + uu];
                red[gate] = s;
            }
            float F = red[0] + gx0;
            float I = red[1] + gx1;
            float G = red[2] + gx2;
            float O = red[3] + gx3;
            creg = sigm(F) * creg + sigm(I) * tanhf(G);
            float h = sigm(O) * tanhf(creg);

            // Write h in both layouts (recurrent: permuted position)
            d_Hts[(size_t)(t + 1) * 32768 + b_ * 1024 + pp] = h;
            d_H2[(size_t)(b_ * 512 + t) * 1024 + bk * 8 + uu] = h;
        }

        // ---- Grid barrier ----
        __syncthreads();   // h writes done; also protects sPart reuse
        __threadfence();
        if (tid == 0) {
            unsigned arrived = atomicAdd(&d_cnt[t], 1u) + 1u;
            if (arrived < NB2) {
                volatile unsigned* vc = d_cnt;
                while (vc[t] < NB2) {}
            }
        }
        __syncthreads();
    }
}

// ------------------------------------------------------------------
// Launch sequence (graph-capturable: kernel launches only)
// ------------------------------------------------------------------
extern "C" void kernel_launch(void* const* d_in, const int* in_sizes, int n_in,
                              void* d_out, int out_size) {
    const float* x    = (const float*)d_in[0];
    const float* W_f  = (const float*)d_in[1];
    const float* b_f  = (const float*)d_in[2];
    const float* W_i  = (const float*)d_in[3];
    const float* b_i  = (const float*)d_in[4];
    const float* W_g  = (const float*)d_in[5];
    const float* b_g  = (const float*)d_in[6];
    const float* W_o  = (const float*)d_in[7];
    const float* b_o  = (const float*)d_in[8];
    const float* W_fc = (const float*)d_in[9];
    const float* b_fc = (const float*)d_in[10];
    float* out = (float*)d_out;

    void *pGx, *pH2, *pWx, *pbx;
    cudaGetSymbolAddress(&pGx, d_Gx);
    cudaGetSymbolAddress(&pH2, d_H2);
    cudaGetSymbolAddress(&pWx, d_Wx);
    cudaGetSymbolAddress(&pbx, d_bx);

    init_kernel<<<128, 256>>>();
    pack_kernel<<<2048, 256>>>(W_f, W_i, W_g, W_o, b_f, b_i, b_g, b_o);

    // Phase 1: Gx = x @ Wx + bx   (M=16384, N=4096, K=512)
    gemm_tf32_bias<<<dim3(32, 128), 256>>>(
        x, (const float*)pWx, (const float*)pbx, (float*)pGx, 16384, 4096, 512);

    // Phase 2: recurrence (persistent)
    lstm_rec<<<NB2, 512>>>(W_f, W_i, W_g, W_o);

    // Phase 3: out = H2 @ W_fc + b_fc   (M=16384, N=512, K=1024)
    gemm_tf32_bias<<<dim3(4, 128), 256>>>(
        (const float*)pH2, W_fc, b_fc, out, 16384, 512, 1024);
}

// round 5
// speedup vs baseline: 1.8258x; 1.5064x over previous
#include <cuda_runtime.h>
#include <cuda_bf16.h>
#include <cuda_fp16.h>
#include <cstdint>

#define NB2 128   // persistent blocks in recurrent kernel (must be <= 148)

// ------------------------------------------------------------------
// Device-global scratch (allocation-free)
// ------------------------------------------------------------------
__device__ float  d_Gx[(size_t)16384 * 4096];      // x@Wx + bias
__device__ float  d_H2[(size_t)16384 * 1024];      // h [b*512+t][j] for final FC
__device__ __half d_Hts[(size_t)513 * 32 * 1024];  // h fp16 [t][b][k_perm] for recurrence
__device__ float  d_Wx[(size_t)512 * 4096];        // packed input-projection weights
__device__ float  d_bx[4096];                      // packed gate biases
__device__ unsigned d_cnt[512];                    // per-step grid-barrier counters

// ------------------------------------------------------------------
// Helpers
// ------------------------------------------------------------------
__device__ __forceinline__ unsigned cvt_tf32(float x) {
    unsigned u;
    asm("cvt.rna.tf32.f32 %0, %1;" : "=r"(u) : "f"(x));
    return u;
}

__device__ __forceinline__ void mma_tf32(float c[4],
                                         unsigned a0, unsigned a1, unsigned a2, unsigned a3,
                                         unsigned b0, unsigned b1) {
    asm volatile(
        "mma.sync.aligned.m16n8k8.row.col.f32.tf32.tf32.f32 "
        "{%0,%1,%2,%3},{%4,%5,%6,%7},{%8,%9},{%0,%1,%2,%3};"
        : "+f"(c[0]), "+f"(c[1]), "+f"(c[2]), "+f"(c[3])
        : "r"(a0), "r"(a1), "r"(a2), "r"(a3), "r"(b0), "r"(b1));
}

__device__ __forceinline__ void mma_f16(float c[4],
                                        unsigned a0, unsigned a1, unsigned a2, unsigned a3,
                                        unsigned b0, unsigned b1) {
    asm volatile(
        "mma.sync.aligned.m16n8k16.row.col.f32.f16.f16.f32 "
        "{%0,%1,%2,%3},{%4,%5,%6,%7},{%8,%9},{%0,%1,%2,%3};"
        : "+f"(c[0]), "+f"(c[1]), "+f"(c[2]), "+f"(c[3])
        : "r"(a0), "r"(a1), "r"(a2), "r"(a3), "r"(b0), "r"(b1));
}

__device__ __forceinline__ float sigm(float x) { return 1.f / (1.f + __expf(-x)); }

// k-permutation for the fp16 h layout: within each 32-k group, thread tig of an
// MMA warp reads one contiguous 16B chunk holding exactly its A-fragment halves.
__device__ __forceinline__ int perm32(int j) {
    int tig = (j & 7) >> 1;
    int a   = (j & 31) >> 4;
    return (j & ~31) + tig * 8 + a * 4 + (j & 1) + 2 * ((j & 15) >> 3);
}

// ------------------------------------------------------------------
// Init: zero h_0 slab and barrier counters (runs every launch/replay)
// ------------------------------------------------------------------
__global__ void init_kernel() {
    int idx = blockIdx.x * blockDim.x + threadIdx.x;
    if (idx < 16384) ((unsigned*)d_Hts)[idx] = 0u;   // 32768 halves
    if (idx < 512) d_cnt[idx] = 0u;
}

// ------------------------------------------------------------------
// Pack Wx = [Wf|Wi|Wg|Wo] rows [0,512), and the gate biases
// ------------------------------------------------------------------
__global__ void pack_kernel(const float* __restrict__ Wf, const float* __restrict__ Wi,
                            const float* __restrict__ Wg, const float* __restrict__ Wo,
                            const float* __restrict__ bf, const float* __restrict__ bi,
                            const float* __restrict__ bg, const float* __restrict__ bo) {
    int idx = blockIdx.x * blockDim.x + threadIdx.x;
    if (idx < 512 * 1024) {
        int k = idx >> 10, j = idx & 1023;
        size_t o = (size_t)k * 4096 + j;
        d_Wx[o]        = Wf[idx];
        d_Wx[o + 1024] = Wi[idx];
        d_Wx[o + 2048] = Wg[idx];
        d_Wx[o + 3072] = Wo[idx];
    }
    if (idx < 1024) {
        d_bx[idx]        = bf[idx];
        d_bx[idx + 1024] = bi[idx];
        d_bx[idx + 2048] = bg[idx];
        d_bx[idx + 3072] = bo[idx];
    }
}

// ------------------------------------------------------------------
// tf32 GEMM: C[M,N] = A[M,K] @ B[K,N] + bias[N]
// 128x128x16 tiles, 8 warps, single-buffered smem (best measured variant).
// ------------------------------------------------------------------
__global__ void __launch_bounds__(256) gemm_tf32_bias(
    const float* __restrict__ A, const float* __restrict__ Bm,
    const float* __restrict__ bias, float* __restrict__ C,
    int M, int N, int K) {
    __shared__ float sA[128 * 20];
    __shared__ float sB[16 * 132];

    const int tid = threadIdx.x;
    const int w = tid >> 5, lane = tid & 31;
    const int g = lane >> 2, tig = lane & 3;
    const int wm = (w >> 2) * 64, wn = (w & 3) * 32;
    const int m0 = blockIdx.y * 128, n0 = blockIdx.x * 128;

    float Cr[4][4][4];
#pragma unroll
    for (int a = 0; a < 4; a++)
#pragma unroll
        for (int b = 0; b < 4; b++)
#pragma unroll
            for (int c = 0; c < 4; c++) Cr[a][b][c] = 0.f;

    const int nk = K / 16;
    for (int kc = 0; kc < nk; kc++) {
        const int k0 = kc * 16;
        __syncthreads();
#pragma unroll
        for (int i = 0; i < 2; i++) {
            int lin = tid + i * 256;
            int r = lin >> 2, q = lin & 3;
            float4 v = *(const float4*)(A + (size_t)(m0 + r) * K + k0 + q * 4);
            *(float4*)(sA + r * 20 + q * 4) = v;
        }
#pragma unroll
        for (int i = 0; i < 2; i++) {
            int lin = tid + i * 256;
            int r = lin >> 5, q = lin & 31;
            float4 v = *(const float4*)(Bm + (size_t)(k0 + r) * N + n0 + q * 4);
            *(float4*)(sB + r * 132 + q * 4) = v;
        }
        __syncthreads();

#pragma unroll
        for (int k8 = 0; k8 < 2; k8++) {
            unsigned bf_[4][2];
#pragma unroll
            for (int nt = 0; nt < 4; nt++) {
                bf_[nt][0] = cvt_tf32(sB[(k8 * 8 + tig) * 132 + wn + nt * 8 + g]);
                bf_[nt][1] = cvt_tf32(sB[(k8 * 8 + tig + 4) * 132 + wn + nt * 8 + g]);
            }
#pragma unroll
            for (int mt = 0; mt < 4; mt++) {
                const float* ap = sA + (wm + mt * 16 + g) * 20 + k8 * 8 + tig;
                unsigned a0 = cvt_tf32(ap[0]);
                unsigned a1 = cvt_tf32(ap[8 * 20]);
                unsigned a2 = cvt_tf32(ap[4]);
                unsigned a3 = cvt_tf32(ap[8 * 20 + 4]);
#pragma unroll
                for (int nt = 0; nt < 4; nt++)
                    mma_tf32(Cr[mt][nt], a0, a1, a2, a3, bf_[nt][0], bf_[nt][1]);
            }
        }
    }

#pragma unroll
    for (int mt = 0; mt < 4; mt++) {
#pragma unroll
        for (int nt = 0; nt < 4; nt++) {
            int row = m0 + wm + mt * 16 + g;
            int col = n0 + wn + nt * 8 + 2 * tig;
            float bx = bias[col], by = bias[col + 1];
            float2 v0 = make_float2(Cr[mt][nt][0] + bx, Cr[mt][nt][1] + by);
            float2 v1 = make_float2(Cr[mt][nt][2] + bx, Cr[mt][nt][3] + by);
            *(float2*)(C + (size_t)row * N + col) = v0;
            *(float2*)(C + (size_t)(row + 8) * N + col) = v1;
        }
    }
}

// ------------------------------------------------------------------
// Persistent recurrent kernel. 128 blocks x 512 threads (16 warps).
// Block bk owns hidden units [bk*8, bk*8+8) x 4 gates. Warp w owns
// K-slice [w*64, w*64+64). Weights as fp16 B-fragments in registers
// (Wr[4][4][2] = 32 regs). h stored fp16, k-permuted so one LDG.128
// per lane per 32-k group = full A fragments for 2 k16 MMA tiles.
// Single-stage reduction into 16 dynamic-smem regions (gate-contiguous
// so the final reduce is 16 x LDS.128). Fence-free acq_rel grid barrier.
// ------------------------------------------------------------------
__global__ void __launch_bounds__(512) lstm_rec(
    const float* __restrict__ Wf, const float* __restrict__ Wi,
    const float* __restrict__ Wg, const float* __restrict__ Wo) {
    extern __shared__ float sPart[];   // 16 regions x 32 rows x 36 floats

    const int tid = threadIdx.x;
    const int w = tid >> 5, lane = tid & 31;
    const int g = lane >> 2, tig = lane & 3;
    const int kw = w * 64;
    const int bk = blockIdx.x;

    // ---- Preload weights as fp16x2 B-fragments (true k order) ----
    const float* Wp[4] = {Wf, Wi, Wg, Wo};
    unsigned Wr[4][4][2];
#pragma unroll
    for (int kt = 0; kt < 4; kt++) {
#pragma unroll
        for (int nt = 0; nt < 4; nt++) {
            const float* ws = Wp[nt] + (size_t)(512 + kw + kt * 16 + 2 * tig) * 1024 + bk * 8 + g;
            __half2 lo = __floats2half2_rn(__ldg(ws), __ldg(ws + 1024));
            __half2 hi = __floats2half2_rn(__ldg(ws + 8 * 1024), __ldg(ws + 9 * 1024));
            Wr[kt][nt][0] = *(unsigned*)&lo;
            Wr[kt][nt][1] = *(unsigned*)&hi;
        }
    }

    // State-thread mapping (first 256 threads): b = tid/8, uu = tid%8
    const int b_ = (tid >> 3) & 31, uu = tid & 7;
    const bool is_state = tid < 256;
    float creg = 0.f;
    const int j = bk * 8 + uu;
    const int ppos = perm32(j);

    // Incremented pointers (avoid per-step 64-bit address math)
    const __half* hrd = d_Hts + kw + tig * 8;                       // += 32768
    __half* hwr = d_Hts + 32768 + (size_t)b_ * 1024 + ppos;         // += 32768
    const float* gxp = d_Gx + (size_t)(b_ * 512) * 4096 + bk * 8 + uu;  // += 4096
    float* h2p = d_H2 + (size_t)(b_ * 512) * 1024 + bk * 8 + uu;    // += 1024
    unsigned* cntp = d_cnt;                                          // += 1

    for (int t = 0; t < 512; t++) {
        // Prefetch this step's input-projection gate values
        float gx0 = 0.f, gx1 = 0.f, gx2 = 0.f, gx3 = 0.f;
        if (is_state) {
            gx0 = __ldcs(gxp);
            gx1 = __ldcs(gxp + 1024);
            gx2 = __ldcs(gxp + 2048);
            gx3 = __ldcs(gxp + 3072);
        }

        // ---- Front-batched h loads: 8 x LDG.128 (max MLP) ----
        uint4 V[2][2][2];   // [kb][mt][row g / g+8]
#pragma unroll
        for (int kb = 0; kb < 2; kb++)
#pragma unroll
            for (int mt = 0; mt < 2; mt++) {
                V[kb][mt][0] = __ldcg((const uint4*)(hrd + kb * 32 + (mt * 16 + g) * 1024));
                V[kb][mt][1] = __ldcg((const uint4*)(hrd + kb * 32 + (mt * 16 + g + 8) * 1024));
            }

        // ---- h_t @ Wh_slice (fp16 HMMA, fp32 accum) ----
        float Cr[2][4][4];
#pragma unroll
        for (int mt = 0; mt < 2; mt++)
#pragma unroll
            for (int nt = 0; nt < 4; nt++)
#pragma unroll
                for (int c = 0; c < 4; c++) Cr[mt][nt][c] = 0.f;

#pragma unroll
        for (int kb = 0; kb < 2; kb++) {
#pragma unroll
            for (int mt = 0; mt < 2; mt++) {
                const uint4& v0 = V[kb][mt][0];
                const uint4& v1 = V[kb][mt][1];
#pragma unroll
                for (int nt = 0; nt < 4; nt++)
                    mma_f16(Cr[mt][nt], v0.x, v1.x, v0.y, v1.y,
                            Wr[2 * kb][nt][0], Wr[2 * kb][nt][1]);
#pragma unroll
                for (int nt = 0; nt < 4; nt++)
                    mma_f16(Cr[mt][nt], v0.z, v1.z, v0.w, v1.w,
                            Wr[2 * kb + 1][nt][0], Wr[2 * kb + 1][nt][1]);
            }
        }

        // ---- Write partials: region w, gate-contiguous layout ----
        {
            float* sp = sPart + w * 1152;
#pragma unroll
            for (int mt = 0; mt < 2; mt++) {
#pragma unroll
                for (int nt = 0; nt < 4; nt++) {
                    int row = mt * 16 + g, c = 2 * tig;
                    sp[row * 36 + c * 4 + nt]           = Cr[mt][nt][0];
                    sp[row * 36 + (c + 1) * 4 + nt]     = Cr[mt][nt][1];
                    sp[(row + 8) * 36 + c * 4 + nt]     = Cr[mt][nt][2];
                    sp[(row + 8) * 36 + (c + 1) * 4 + nt] = Cr[mt][nt][3];
                }
            }
        }
        __syncthreads();

        // ---- Final reduce (16 x LDS.128) + gates + state update ----
        if (is_state) {
            const float4* rp = (const float4*)sPart + (b_ * 9 + uu);
            float4 s0 = rp[0], s1 = rp[288];
#pragma unroll
            for (int r = 2; r < 16; r += 2) {
                float4 a = rp[r * 288], b = rp[(r + 1) * 288];
                s0.x += a.x; s0.y += a.y; s0.z += a.z; s0.w += a.w;
                s1.x += b.x; s1.y += b.y; s1.z += b.z; s1.w += b.w;
            }
            float F = s0.x + s1.x + gx0;
            float I = s0.y + s1.y + gx1;
            float G = s0.z + s1.z + gx2;
            float O = s0.w + s1.w + gx3;
            creg = sigm(F) * creg + sigm(I) * tanhf(G);
            float h = sigm(O) * tanhf(creg);

            *hwr = __float2half_rn(h);
            *h2p = h;
        }
        __syncthreads();   // h stores + sPart reads complete

        // ---- Fence-free grid barrier (acq_rel atomic + acquire poll) ----
        if (tid == 0) {
            unsigned ret;
            asm volatile("atom.acq_rel.gpu.add.u32 %0, [%1], %2;"
                         : "=r"(ret) : "l"(cntp), "r"(1u) : "memory");
            if (ret + 1u < NB2) {
                unsigned v;
                do {
                    asm volatile("ld.acquire.gpu.u32 %0, [%1];"
                                 : "=r"(v) : "l"(cntp) : "memory");
                } while (v < NB2);
            }
        }
        __syncthreads();

        hrd += 32768; hwr += 32768; gxp += 4096; h2p += 1024; cntp += 1;
    }
}

// ------------------------------------------------------------------
// Launch sequence (graph-capturable: kernel launches only)
// ------------------------------------------------------------------
extern "C" void kernel_launch(void* const* d_in, const int* in_sizes, int n_in,
                              void* d_out, int out_size) {
    const float* x    = (const float*)d_in[0];
    const float* W_f  = (const float*)d_in[1];
    const float* b_f  = (const float*)d_in[2];
    const float* W_i  = (const float*)d_in[3];
    const float* b_i  = (const float*)d_in[4];
    const float* W_g  = (const float*)d_in[5];
    const float* b_g  = (const float*)d_in[6];
    const float* W_o  = (const float*)d_in[7];
    const float* b_o  = (const float*)d_in[8];
    const float* W_fc = (const float*)d_in[9];
    const float* b_fc = (const float*)d_in[10];
    float* out = (float*)d_out;

    void *pGx, *pH2, *pWx, *pbx;
    cudaGetSymbolAddress(&pGx, d_Gx);
    cudaGetSymbolAddress(&pH2, d_H2);
    cudaGetSymbolAddress(&pWx, d_Wx);
    cudaGetSymbolAddress(&pbx, d_bx);

    static bool attr_set = false;
    if (!attr_set) {
        cudaFuncSetAttribute(lstm_rec, cudaFuncAttributeMaxDynamicSharedMemorySize,
                             16 * 1152 * 4);
        attr_set = true;
    }

    init_kernel<<<128, 256>>>();
    pack_kernel<<<2048, 256>>>(W_f, W_i, W_g, W_o, b_f, b_i, b_g, b_o);

    // Phase 1: Gx = x @ Wx + bx   (M=16384, N=4096, K=512)
    gemm_tf32_bias<<<dim3(32, 128), 256>>>(
        x, (const float*)pWx, (const float*)pbx, (float*)pGx, 16384, 4096, 512);

    // Phase 2: recurrence (persistent)
    lstm_rec<<<NB2, 512, 16 * 1152 * 4>>>(W_f, W_i, W_g, W_o);

    // Phase 3: out = H2 @ W_fc + b_fc   (M=16384, N=512, K=1024)
    gemm_tf32_bias<<<dim3(4, 128), 256>>>(
        (const float*)pH2, W_fc, b_fc, out, 16384, 512, 1024);
}